// round 6
// baseline (speedup 1.0000x reference)
#include <cuda_runtime.h>
#include <cuda_bf16.h>
#include <math.h>

// Problem dims (fixed by the reference)
#define NP      128      // proposals
#define NB      16       // neighbors per proposal
#define KK      64       // knn per node
#define LL      1024     // NB*KK flattened group size
#define MM      450      // FINEMATCH_MAX_POINT
#define DD      256      // feature dim
#define NPTS_C  20000

// ---------------------------------------------------------------------------
// Single fused kernel: one block (1024 threads) per proposal.
// Phase 1: mask eval + stable stream compaction into SHARED memory,
//          resolving fidx + point coords per valid slot.
// Phase 2: 32 warps gather the 450 output rows (warp w -> rows w, w+32, ...).
//
// Output layout (float32, concatenated flat):
//   [0,              P*M*3)            points
//   [P*M*3,          P*M*3 + P*M*D)    feats
//   [P*M*3 + P*M*D,  end)              mask (1.0f / 0.0f)
//
// Resample index: single-rounded fp32 floor((i*n)/450); i*n < 2^24 so the
// product is exact and IEEE divide is exact at integer quotients —
// bit-matches XLA's rewritten (i/M)*n. Stable ascending-j compaction matches
// jnp.argsort(stable) of !mask.
// ---------------------------------------------------------------------------
__global__ void __launch_bounds__(1024, 1) fused_kernel(
    const unsigned int*  __restrict__ nb_mask,     // [P, NB] bool-as-u32
    const int*           __restrict__ seed_idx,    // [P, NB] int32
    const unsigned int*  __restrict__ knn_masks,   // [NNODES, K] bool-as-u32
    const int*           __restrict__ knn_idx,     // [NNODES, K]
    const float*         __restrict__ knn_points,  // [NNODES, K, 3]
    const float*         __restrict__ feats,       // [NPTS, D]
    float*               __restrict__ out)
{
    __shared__ int   s_fidx[LL];       // compacted feature indices
    __shared__ float s_px[LL];         // compacted point coords
    __shared__ float s_py[LL];
    __shared__ float s_pz[LL];
    __shared__ int   s_wsum[32];
    __shared__ int   s_woff[32];
    __shared__ int   s_n;

    const int p    = blockIdx.x;
    const int j    = threadIdx.x;      // 0..1023
    const int lane = j & 31;
    const int warp = j >> 5;           // 0..31

    // ---------------- Phase 1: compaction ----------------
    {
        const int nb = j >> 6;         // j / K
        const int kk = j & 63;         // j % K
        const int node = seed_idx[p * NB + nb];
        const int gk   = node * KK + kk;
        const bool m = (knn_masks[gk] != 0u) && (nb_mask[p * NB + nb] != 0u);

        // issue the gather loads early (predicated); latency overlaps the scan
        int   fi = 0;
        float px = 0.f, py = 0.f, pz = 0.f;
        if (m) {
            fi = knn_idx[gk];
            px = knn_points[gk * 3 + 0];
            py = knn_points[gk * 3 + 1];
            pz = knn_points[gk * 3 + 2];
        }

        const unsigned ball = __ballot_sync(0xffffffffu, m);
        const int wpre = __popc(ball & ((1u << lane) - 1u));
        if (lane == 0) s_wsum[warp] = __popc(ball);
        __syncthreads();

        if (warp == 0) {
            int v = s_wsum[lane];
            int s = v;
            #pragma unroll
            for (int d = 1; d < 32; d <<= 1) {
                int t = __shfl_up_sync(0xffffffffu, s, d);
                if (lane >= d) s += t;
            }
            s_woff[lane] = s - v;           // exclusive prefix of warp totals
            if (lane == 31) s_n = s;        // total valid count
        }
        __syncthreads();

        if (m) {
            const int slot = s_woff[warp] + wpre;
            s_fidx[slot] = fi;
            s_px[slot] = px;
            s_py[slot] = py;
            s_pz[slot] = pz;
        }
        __syncthreads();
    }

    // ---------------- Phase 2: gather 450 rows ----------------
    const int n  = s_n;
    const int nm = (n < MM) ? n : MM;
    const bool big = (n > MM);

    const size_t FEATS_OFF = (size_t)NP * MM * 3;
    const size_t MASK_OFF  = FEATS_OFF + (size_t)NP * MM * DD;

    for (int i = warp; i < MM; i += 32) {
        const size_t row = (size_t)p * MM + i;
        float4* dst = (float4*)(out + FEATS_OFF + row * DD);

        if (i < nm) {
            int local;
            if (big) {
                local = __float2int_rd(__fdiv_rn((float)(i * n), (float)MM));
            } else {
                local = i;
            }
            if (local > LL - 1) local = LL - 1;

            const int fidx = s_fidx[local];   // smem broadcast, 29 cyc

            if (lane == 0) {
                out[row * 3 + 0]   = s_px[local];
                out[row * 3 + 1]   = s_py[local];
                out[row * 3 + 2]   = s_pz[local];
                out[MASK_OFF + row] = 1.0f;
            }

            if (fidx >= 0 && fidx < NPTS_C) {
                const float4* src = (const float4*)(feats + (size_t)fidx * DD);
                const float4 a = __ldg(src + lane);
                const float4 b = __ldg(src + lane + 32);
                dst[lane]      = a;
                dst[lane + 32] = b;
            } else {
                const float4 z = make_float4(0.f, 0.f, 0.f, 0.f);
                dst[lane] = z;
                dst[lane + 32] = z;
            }
        } else {
            if (lane == 0) {
                out[row * 3 + 0]   = 0.0f;
                out[row * 3 + 1]   = 0.0f;
                out[row * 3 + 2]   = 0.0f;
                out[MASK_OFF + row] = 0.0f;
            }
            const float4 z = make_float4(0.f, 0.f, 0.f, 0.f);
            dst[lane] = z;
            dst[lane + 32] = z;
        }
    }
}

extern "C" void kernel_launch(void* const* d_in, const int* in_sizes, int n_in,
                              void* d_out, int out_size)
{
    // metadata order (= setup_inputs dict order):
    // 0: ref_node_neighbor_mask   (P, NB)        bool -> u32
    // 1: ref_seed_neighbor_indices(P, NB)        int32
    // 2: ref_node_knn_masks       (NNODES, K)    bool -> u32
    // 3: ref_node_knn_points      (NNODES, K, 3) float32
    // 4: ref_node_knn_indices     (NNODES, K)    int32
    // 5: ref_feats_m              (NPTS, D)      float32
    const unsigned int*  nb_mask    = (const unsigned int*)d_in[0];
    const int*           seed_idx   = (const int*)d_in[1];
    const unsigned int*  knn_masks  = (const unsigned int*)d_in[2];
    const float*         knn_points = (const float*)d_in[3];
    const int*           knn_idx    = (const int*)d_in[4];
    const float*         feats      = (const float*)d_in[5];
    float* out = (float*)d_out;

    fused_kernel<<<NP, 1024>>>(nb_mask, seed_idx, knn_masks, knn_idx,
                               knn_points, feats, out);
}

// round 9
// speedup vs baseline: 1.2473x; 1.2473x over previous
#include <cuda_runtime.h>
#include <cuda_bf16.h>
#include <math.h>

// Problem dims (fixed by the reference)
#define NP      128      // proposals
#define NB      16       // neighbors per proposal
#define KK      64       // knn per node
#define LL      1024     // NB*KK flattened group size
#define MM      450      // FINEMATCH_MAX_POINT
#define DD      256      // feature dim
#define NPTS_C  20000
#define NROWS   (NP * MM)   // 57600

// Scratch: per-output-row resolved feature index (-1 => zero row)
__device__ int g_rowfidx[NROWS];

// ---------------------------------------------------------------------------
// Kernel A: mask eval + stable compaction (smem) + resample + write points,
// mask, and per-row feature indices. One block (1024 thr) per proposal.
// Stable ascending-j order matches jnp.argsort(stable) of !mask.
// Resample: single-rounded fp32 floor((i*n)/450); i*n < 2^24 exact, IEEE
// divide exact at integer quotients — bit-matches XLA's (i/M)*n rewrite.
// ---------------------------------------------------------------------------
__global__ void __launch_bounds__(1024) compact_kernel(
    const unsigned int*  __restrict__ nb_mask,     // [P, NB] bool-as-u32
    const int*           __restrict__ seed_idx,    // [P, NB] int32
    const unsigned int*  __restrict__ knn_masks,   // [NNODES, K] bool-as-u32
    const int*           __restrict__ knn_idx,     // [NNODES, K]
    const float*         __restrict__ knn_points,  // [NNODES, K, 3]
    float*               __restrict__ out)
{
    __shared__ int   s_fidx[LL];
    __shared__ float s_px[LL];
    __shared__ float s_py[LL];
    __shared__ float s_pz[LL];
    __shared__ int   s_wsum[32];
    __shared__ int   s_woff[32];
    __shared__ int   s_n;

    const int p    = blockIdx.x;
    const int j    = threadIdx.x;      // 0..1023
    const int lane = j & 31;
    const int warp = j >> 5;

    // ---- Phase 1: compaction into smem ----
    {
        const int nb = j >> 6;
        const int kk = j & 63;
        const int node = seed_idx[p * NB + nb];
        const int gk   = node * KK + kk;
        const bool m = (knn_masks[gk] != 0u) && (nb_mask[p * NB + nb] != 0u);

        int   fi = 0;
        float px = 0.f, py = 0.f, pz = 0.f;
        if (m) {
            fi = knn_idx[gk];
            px = knn_points[gk * 3 + 0];
            py = knn_points[gk * 3 + 1];
            pz = knn_points[gk * 3 + 2];
        }

        const unsigned ball = __ballot_sync(0xffffffffu, m);
        const int wpre = __popc(ball & ((1u << lane) - 1u));
        if (lane == 0) s_wsum[warp] = __popc(ball);
        __syncthreads();

        if (warp == 0) {
            int v = s_wsum[lane];
            int s = v;
            #pragma unroll
            for (int d = 1; d < 32; d <<= 1) {
                int t = __shfl_up_sync(0xffffffffu, s, d);
                if (lane >= d) s += t;
            }
            s_woff[lane] = s - v;
            if (lane == 31) s_n = s;
        }
        __syncthreads();

        if (m) {
            const int slot = s_woff[warp] + wpre;
            s_fidx[slot] = fi;
            s_px[slot] = px;
            s_py[slot] = py;
            s_pz[slot] = pz;
        }
        __syncthreads();
    }

    // ---- Phase 2: resample, write points + mask + row fidx ----
    const int n  = s_n;
    const int nm = (n < MM) ? n : MM;

    const size_t MASK_OFF = (size_t)NP * MM * 3 + (size_t)NP * MM * DD;

    const int i = j;
    if (i < MM) {
        const size_t row = (size_t)p * MM + i;
        if (i < nm) {
            int local;
            if (n > MM) {
                local = __float2int_rd(__fdiv_rn((float)(i * n), (float)MM));
            } else {
                local = i;
            }
            if (local > LL - 1) local = LL - 1;

            out[row * 3 + 0]    = s_px[local];
            out[row * 3 + 1]    = s_py[local];
            out[row * 3 + 2]    = s_pz[local];
            out[MASK_OFF + row] = 1.0f;
            const int f = s_fidx[local];
            g_rowfidx[row] = (f >= 0 && f < NPTS_C) ? f : -1;
        } else {
            out[row * 3 + 0]    = 0.0f;
            out[row * 3 + 1]    = 0.0f;
            out[row * 3 + 2]    = 0.0f;
            out[MASK_OFF + row] = 0.0f;
            g_rowfidx[row] = -1;
        }
    }
}

// ---------------------------------------------------------------------------
// Kernel B: pure feature copy. 256 thr/block, each warp handles 4 rows.
// Lanes 0-3 read 4 contiguous fidx (one 16B transaction), shfl-broadcast,
// then 8 independent float4 loads are issued before any store (MLP=8).
// 57600 rows / 4 = 14400 warps = 1800 blocks exactly.
// ---------------------------------------------------------------------------
__global__ void __launch_bounds__(256) feat_kernel(
    const float* __restrict__ feats,    // [NPTS, D]
    float*       __restrict__ out)
{
    const int warp = threadIdx.x >> 5;           // 0..7
    const int lane = threadIdx.x & 31;
    const int rowbase = (blockIdx.x * 8 + warp) * 4;

    const size_t FEATS_OFF = (size_t)NP * MM * 3;

    int f = -1;
    if (lane < 4) f = g_rowfidx[rowbase + lane];
    int fr[4];
    fr[0] = __shfl_sync(0xffffffffu, f, 0);
    fr[1] = __shfl_sync(0xffffffffu, f, 1);
    fr[2] = __shfl_sync(0xffffffffu, f, 2);
    fr[3] = __shfl_sync(0xffffffffu, f, 3);

    const float4 z = make_float4(0.f, 0.f, 0.f, 0.f);
    float4 a[4], b[4];
    #pragma unroll
    for (int k = 0; k < 4; k++) {
        if (fr[k] >= 0) {
            const float4* src = (const float4*)(feats + (size_t)fr[k] * DD);
            a[k] = __ldg(src + lane);
            b[k] = __ldg(src + lane + 32);
        } else {
            a[k] = z;
            b[k] = z;
        }
    }
    #pragma unroll
    for (int k = 0; k < 4; k++) {
        float4* dst = (float4*)(out + FEATS_OFF + (size_t)(rowbase + k) * DD);
        dst[lane]      = a[k];
        dst[lane + 32] = b[k];
    }
}

extern "C" void kernel_launch(void* const* d_in, const int* in_sizes, int n_in,
                              void* d_out, int out_size)
{
    // metadata order (= setup_inputs dict order):
    // 0: ref_node_neighbor_mask   (P, NB)        bool -> u32
    // 1: ref_seed_neighbor_indices(P, NB)        int32
    // 2: ref_node_knn_masks       (NNODES, K)    bool -> u32
    // 3: ref_node_knn_points      (NNODES, K, 3) float32
    // 4: ref_node_knn_indices     (NNODES, K)    int32
    // 5: ref_feats_m              (NPTS, D)      float32
    const unsigned int*  nb_mask    = (const unsigned int*)d_in[0];
    const int*           seed_idx   = (const int*)d_in[1];
    const unsigned int*  knn_masks  = (const unsigned int*)d_in[2];
    const float*         knn_points = (const float*)d_in[3];
    const int*           knn_idx    = (const int*)d_in[4];
    const float*         feats      = (const float*)d_in[5];
    float* out = (float*)d_out;

    compact_kernel<<<NP, 1024>>>(nb_mask, seed_idx, knn_masks, knn_idx,
                                 knn_points, out);

    feat_kernel<<<NROWS / 32, 256>>>(feats, out);   // 1800 blocks x 8 warps x 4 rows
}